// round 3
// baseline (speedup 1.0000x reference)
#include <cuda_runtime.h>
#include <cuda_bf16.h>
#include <math.h>

// Problem constants
#define BATCH   2
#define SEQLEN  2048
#define DMODEL  2048
#define NHEADS  16
#define DHEAD   128
#define MTOT    (BATCH * SEQLEN)      // 4096
#define NEG_BIG (-1e30f)

typedef unsigned long long ull;

// ---- packed f32x2 helpers (Blackwell 2x FP32 path; PTX-only, ptxas won't fuse)
__device__ __forceinline__ ull pack2(float lo, float hi) {
    ull r; asm("mov.b64 %0, {%1,%2};" : "=l"(r) : "f"(lo), "f"(hi)); return r;
}
__device__ __forceinline__ void fma2(ull& d, ull a, ull b) {
    asm("fma.rn.f32x2 %0, %1, %2, %3;" : "=l"(d) : "l"(a), "l"(b), "l"(d));
}
__device__ __forceinline__ void mul2(ull& d, ull a, ull b) {
    asm("mul.rn.f32x2 %0, %1, %2;" : "=l"(d) : "l"(a), "l"(b));
}
__device__ __forceinline__ float2 unpack2(ull v) {
    float lo, hi; asm("mov.b64 {%0,%1}, %2;" : "=f"(lo), "=f"(hi) : "l"(v));
    return make_float2(lo, hi);
}

// Scratch (device globals: allocation-free rule).
// Only referenced from device code (host address-of = shadow symbol, the R1 bug).
__device__ float g_q[(size_t)MTOT * DMODEL];
__device__ float g_k[(size_t)MTOT * DMODEL];
__device__ float g_v[(size_t)MTOT * DMODEL];
__device__ float g_z[(size_t)MTOT * DMODEL];

// ---------------------------------------------------------------------------
// Kernel 1: fused QKV projection (128x128x8 tile, 8x8/thread, f32x2 FMA).
// grid = (M/128, NHEADS, 3), block = 256.
// ---------------------------------------------------------------------------
__global__ void __launch_bounds__(256) qkv_gemm_kernel(
    const float* __restrict__ x,
    const float* __restrict__ Wq, const float* __restrict__ Wk, const float* __restrict__ Wv,
    const float* __restrict__ bQ, const float* __restrict__ bK, const float* __restrict__ bV)
{
    const int mBase = blockIdx.x * 128;
    const int h     = blockIdx.y;
    const int which = blockIdx.z;

    const float* W    = (which == 0) ? Wq : (which == 1) ? Wk : Wv;
    const float* bias = (which == 0) ? bQ : (which == 1) ? bK : bV;
    float* out        = (which == 0) ? g_q : (which == 1) ? g_k : g_v;

    const float* Wh = W + (size_t)h * DMODEL * DHEAD;   // [2048,128] row-major

    __shared__ float As[8][128];   // transposed A: As[k][m]
    __shared__ float Bs[8][132];   // B tile (row pad; 132*4=528B, 16B-aligned rows)

    const int tid = threadIdx.x;
    const int tx = tid & 15;       // col block (tx*8)
    const int ty = tid >> 4;       // row block (ty*8)

    const int arow = tid >> 1;            // 0..127
    const int ac4  = (tid & 1) * 4;       // 0 or 4
    const int brow = tid >> 5;            // 0..7
    const int bcol = (tid & 31) * 4;      // 0..124

    ull acc2[8][4];
#pragma unroll
    for (int i = 0; i < 8; i++)
#pragma unroll
        for (int j = 0; j < 4; j++) acc2[i][j] = 0ULL;

    for (int k0 = 0; k0 < DMODEL; k0 += 8) {
        float4 aval = *(const float4*)&x[(size_t)(mBase + arow) * DMODEL + k0 + ac4];
        float4 bval = *(const float4*)&Wh[(size_t)(k0 + brow) * DHEAD + bcol];
        __syncthreads();   // previous compute done before overwrite
        As[ac4 + 0][arow] = aval.x;
        As[ac4 + 1][arow] = aval.y;
        As[ac4 + 2][arow] = aval.z;
        As[ac4 + 3][arow] = aval.w;
        *(float4*)&Bs[brow][bcol] = bval;
        __syncthreads();

#pragma unroll
        for (int kk = 0; kk < 8; kk++) {
            float av[8];
            *(float4*)&av[0] = *(const float4*)&As[kk][ty * 8];
            *(float4*)&av[4] = *(const float4*)&As[kk][ty * 8 + 4];
            longlong2 bb0 = *(const longlong2*)&Bs[kk][tx * 8];
            longlong2 bb1 = *(const longlong2*)&Bs[kk][tx * 8 + 4];
            ull bv2[4] = { (ull)bb0.x, (ull)bb0.y, (ull)bb1.x, (ull)bb1.y };
#pragma unroll
            for (int i = 0; i < 8; i++) {
                ull a2 = pack2(av[i], av[i]);   // alu-pipe mov, fma pipe untouched
#pragma unroll
                for (int j = 0; j < 4; j++)
                    fma2(acc2[i][j], a2, bv2[j]);
            }
        }
    }

#pragma unroll
    for (int i = 0; i < 8; i++) {
        const size_t row = (size_t)(mBase + ty * 8 + i);
#pragma unroll
        for (int j = 0; j < 4; j++) {
            float2 v = unpack2(acc2[i][j]);
            const int col = tx * 8 + j * 2;
            out[row * DMODEL + h * DHEAD + col]     = v.x + bias[h * DHEAD + col];
            out[row * DMODEL + h * DHEAD + col + 1] = v.y + bias[h * DHEAD + col + 1];
        }
    }
}

// ---------------------------------------------------------------------------
// Kernel 2: fused causal attention (flash-style, fp32, f32x2 FMA).
// grid = (SEQLEN/64, NHEADS, BATCH), block = 256 threads.
// ---------------------------------------------------------------------------
#define QPAD 132   // 528B rows: 16B-aligned
#define PPAD 68    // 272B rows: 8B-aligned (pair loads)

__global__ void __launch_bounds__(256) attn_kernel()
{
    const int qt = blockIdx.x;
    const int h  = blockIdx.y;
    const int b  = blockIdx.z;
    const int qBase = qt * 64;

    extern __shared__ float sm[];
    float* Qs  = sm;                        // [64][QPAD]
    float* Ks  = Qs + 64 * QPAD;            // [64][QPAD]
    float* Vs  = Ks + 64 * QPAD;            // [64][QPAD]
    float* Ps  = Vs + 64 * QPAD;            // [64][PPAD]
    float* Red = Ps + 64 * PPAD;            // [64][16]

    const int tid = threadIdx.x;
    const int tx = tid & 15;
    const int ty = tid >> 4;

    const float scale = 0.08838834764831845f;  // 1/sqrt(128)

    // Load Q tile
    {
        const size_t baseQ = ((size_t)(b * SEQLEN + qBase) * NHEADS + h) * DHEAD;
        for (int i = tid; i < 64 * 32; i += 256) {
            int r = i >> 5, c4 = (i & 31) << 2;
            *(float4*)&Qs[r * QPAD + c4] =
                *(const float4*)&g_q[baseQ + (size_t)r * NHEADS * DHEAD + c4];
        }
    }

    float m_i[4], l_i[4];
    ull o2[4][8];
#pragma unroll
    for (int i = 0; i < 4; i++) {
        m_i[i] = NEG_BIG; l_i[i] = 0.f;
#pragma unroll
        for (int j = 0; j < 8; j++) o2[i][j] = 0ULL;
    }

    const int nkt = qt + 1;   // causal: key tiles 0..qt
    for (int kt = 0; kt < nkt; kt++) {
        const int kBase = kt * 64;
        __syncthreads();   // previous iteration reads done; also orders Q load
        {
            const size_t baseK = ((size_t)(b * SEQLEN + kBase) * NHEADS + h) * DHEAD;
            for (int i = tid; i < 64 * 32; i += 256) {
                int r = i >> 5, c4 = (i & 31) << 2;
                size_t g = baseK + (size_t)r * NHEADS * DHEAD + c4;
                *(float4*)&Ks[r * QPAD + c4] = *(const float4*)&g_k[g];
                *(float4*)&Vs[r * QPAD + c4] = *(const float4*)&g_v[g];
            }
        }
        __syncthreads();

        // S = Q K^T  (packed along reduction dim; horizontal add at end)
        ull s2[4][4];
#pragma unroll
        for (int i = 0; i < 4; i++)
#pragma unroll
            for (int j = 0; j < 4; j++) s2[i][j] = 0ULL;

#pragma unroll 4
        for (int e4 = 0; e4 < 32; e4++) {
            longlong2 a2[4], b2[4];
#pragma unroll
            for (int i = 0; i < 4; i++)
                a2[i] = *(const longlong2*)&Qs[(i * 16 + ty) * QPAD + e4 * 4];
#pragma unroll
            for (int j = 0; j < 4; j++)
                b2[j] = *(const longlong2*)&Ks[(j * 16 + tx) * QPAD + e4 * 4];
#pragma unroll
            for (int i = 0; i < 4; i++)
#pragma unroll
                for (int j = 0; j < 4; j++) {
                    fma2(s2[i][j], (ull)a2[i].x, (ull)b2[j].x);
                    fma2(s2[i][j], (ull)a2[i].y, (ull)b2[j].y);
                }
        }

        float s[4][4];
#pragma unroll
        for (int i = 0; i < 4; i++)
#pragma unroll
            for (int j = 0; j < 4; j++) {
                float2 v = unpack2(s2[i][j]);
                s[i][j] = v.x + v.y;
            }

        // scale + causal mask
#pragma unroll
        for (int i = 0; i < 4; i++) {
            const int qi = qBase + i * 16 + ty;
#pragma unroll
            for (int j = 0; j < 4; j++) {
                const int ki = kBase + j * 16 + tx;
                s[i][j] = (ki <= qi) ? s[i][j] * scale : NEG_BIG;
            }
        }

        // row max (across the 16 tx slots sharing a row)
#pragma unroll
        for (int i = 0; i < 4; i++) {
            float mm = s[i][0];
#pragma unroll
            for (int j = 1; j < 4; j++) mm = fmaxf(mm, s[i][j]);
            Red[(i * 16 + ty) * 16 + tx] = mm;
        }
        __syncthreads();

        float mnew[4], alpha[4];
#pragma unroll
        for (int i = 0; i < 4; i++) {
            float mm = m_i[i];
            const int r = (i * 16 + ty) * 16;
#pragma unroll
            for (int t = 0; t < 16; t++) mm = fmaxf(mm, Red[r + t]);
            mnew[i] = mm;
            alpha[i] = __expf(m_i[i] - mm);   // m_i=NEG_BIG on first tile -> 0
            m_i[i] = mm;
        }

        // p = exp(s - mnew), local row sums
        float p[4][4], ls[4];
#pragma unroll
        for (int i = 0; i < 4; i++) {
            float ssum = 0.f;
#pragma unroll
            for (int j = 0; j < 4; j++) {
                float pv = __expf(s[i][j] - mnew[i]);
                p[i][j] = pv;
                ssum += pv;
            }
            ls[i] = ssum;
        }
        __syncthreads();  // Red max reads done before sum writes
#pragma unroll
        for (int i = 0; i < 4; i++) {
            Red[(i * 16 + ty) * 16 + tx] = ls[i];
#pragma unroll
            for (int j = 0; j < 4; j++)
                Ps[(i * 16 + ty) * PPAD + (j * 16 + tx)] = p[i][j];
        }
        __syncthreads();

#pragma unroll
        for (int i = 0; i < 4; i++) {
            float ssum = 0.f;
            const int r = (i * 16 + ty) * 16;
#pragma unroll
            for (int t = 0; t < 16; t++) ssum += Red[r + t];
            l_i[i] = l_i[i] * alpha[i] + ssum;
            ull al2 = pack2(alpha[i], alpha[i]);
#pragma unroll
            for (int j = 0; j < 8; j++) mul2(o2[i][j], o2[i][j], al2);
        }

        // O += P V  (packed along jj pairs; lanes hold even/odd-jj partials)
#pragma unroll 2
        for (int jj = 0; jj < 64; jj += 2) {
            ull pa2[4], vb2[8];
#pragma unroll
            for (int i = 0; i < 4; i++)
                pa2[i] = *(const ull*)&Ps[(i * 16 + ty) * PPAD + jj];
#pragma unroll
            for (int j = 0; j < 8; j++)
                vb2[j] = pack2(Vs[jj * QPAD + j * 16 + tx],
                               Vs[(jj + 1) * QPAD + j * 16 + tx]);
#pragma unroll
            for (int i = 0; i < 4; i++)
#pragma unroll
                for (int j = 0; j < 8; j++)
                    fma2(o2[i][j], pa2[i], vb2[j]);
        }
    }

    // normalize + write z[b, q, h, :]
#pragma unroll
    for (int i = 0; i < 4; i++) {
        const size_t row = (size_t)(b * SEQLEN + qBase + i * 16 + ty);
        const float inv = 1.f / l_i[i];
#pragma unroll
        for (int j = 0; j < 8; j++) {
            float2 v = unpack2(o2[i][j]);
            g_z[(row * NHEADS + h) * DHEAD + j * 16 + tx] = (v.x + v.y) * inv;
        }
    }
}

// ---------------------------------------------------------------------------
// Kernel 3: output projection (f32x2 FMA). out = z @ W_O + b_O
// grid = (M/128, DMODEL/128), block = 256.
// ---------------------------------------------------------------------------
__global__ void __launch_bounds__(256) out_gemm_kernel(
    const float* __restrict__ Wo, const float* __restrict__ bO,
    float* __restrict__ out)
{
    const int mBase = blockIdx.x * 128;
    const int nBase = blockIdx.y * 128;

    __shared__ float As[8][128];
    __shared__ float Bs[8][132];

    const int tid = threadIdx.x;
    const int tx = tid & 15;
    const int ty = tid >> 4;

    const int arow = tid >> 1;
    const int ac4  = (tid & 1) * 4;
    const int brow = tid >> 5;
    const int bcol = (tid & 31) * 4;

    ull acc2[8][4];
#pragma unroll
    for (int i = 0; i < 8; i++)
#pragma unroll
        for (int j = 0; j < 4; j++) acc2[i][j] = 0ULL;

    for (int k0 = 0; k0 < DMODEL; k0 += 8) {
        float4 aval = *(const float4*)&g_z[(size_t)(mBase + arow) * DMODEL + k0 + ac4];
        float4 bval = *(const float4*)&Wo[(size_t)(k0 + brow) * DMODEL + nBase + bcol];
        __syncthreads();
        As[ac4 + 0][arow] = aval.x;
        As[ac4 + 1][arow] = aval.y;
        As[ac4 + 2][arow] = aval.z;
        As[ac4 + 3][arow] = aval.w;
        *(float4*)&Bs[brow][bcol] = bval;
        __syncthreads();

#pragma unroll
        for (int kk = 0; kk < 8; kk++) {
            float av[8];
            *(float4*)&av[0] = *(const float4*)&As[kk][ty * 8];
            *(float4*)&av[4] = *(const float4*)&As[kk][ty * 8 + 4];
            longlong2 bb0 = *(const longlong2*)&Bs[kk][tx * 8];
            longlong2 bb1 = *(const longlong2*)&Bs[kk][tx * 8 + 4];
            ull bv2[4] = { (ull)bb0.x, (ull)bb0.y, (ull)bb1.x, (ull)bb1.y };
#pragma unroll
            for (int i = 0; i < 8; i++) {
                ull a2 = pack2(av[i], av[i]);
#pragma unroll
                for (int j = 0; j < 4; j++)
                    fma2(acc2[i][j], a2, bv2[j]);
            }
        }
    }

#pragma unroll
    for (int i = 0; i < 8; i++) {
        const size_t row = (size_t)(mBase + ty * 8 + i);
#pragma unroll
        for (int j = 0; j < 4; j++) {
            float2 v = unpack2(acc2[i][j]);
            const int col = nBase + tx * 8 + j * 2;
            out[row * DMODEL + col]     = v.x + bO[col];
            out[row * DMODEL + col + 1] = v.y + bO[col + 1];
        }
    }
}

// ---------------------------------------------------------------------------
// Launch
// ---------------------------------------------------------------------------
extern "C" void kernel_launch(void* const* d_in, const int* in_sizes, int n_in,
                              void* d_out, int out_size)
{
    const float* x  = (const float*)d_in[0];
    const float* Wq = (const float*)d_in[1];
    const float* Wk = (const float*)d_in[2];
    const float* Wv = (const float*)d_in[3];
    const float* Wo = (const float*)d_in[4];
    const float* bQ = (const float*)d_in[5];
    const float* bK = (const float*)d_in[6];
    const float* bV = (const float*)d_in[7];
    const float* bO = (const float*)d_in[8];
    float* out = (float*)d_out;

    // 1) QKV projections
    qkv_gemm_kernel<<<dim3(MTOT / 128, NHEADS, 3), 256>>>(x, Wq, Wk, Wv, bQ, bK, bV);

    // 2) fused causal attention
    const int smem_bytes = (3 * 64 * QPAD + 64 * PPAD + 64 * 16) * (int)sizeof(float);
    static bool attr_set = false;
    if (!attr_set) {
        cudaFuncSetAttribute(attn_kernel, cudaFuncAttributeMaxDynamicSharedMemorySize, smem_bytes);
        attr_set = true;
    }
    attn_kernel<<<dim3(SEQLEN / 64, NHEADS, BATCH), 256, smem_bytes>>>();

    // 3) output projection
    out_gemm_kernel<<<dim3(MTOT / 128, DMODEL / 128), 256>>>(Wo, bO, out);

    (void)in_sizes; (void)n_in; (void)out_size;
}

// round 4
// speedup vs baseline: 1.4987x; 1.4987x over previous
#include <cuda_runtime.h>
#include <cuda_bf16.h>
#include <math.h>

// Problem constants
#define BATCH   2
#define SEQLEN  2048
#define DMODEL  2048
#define NHEADS  16
#define DHEAD   128
#define MTOT    (BATCH * SEQLEN)      // 4096
#define NEG_BIG (-1e30f)

typedef unsigned int u32;
typedef unsigned long long ull;

// ---- packed f32x2 helpers (used by attention kernel)
__device__ __forceinline__ ull pack2(float lo, float hi) {
    ull r; asm("mov.b64 %0, {%1,%2};" : "=l"(r) : "f"(lo), "f"(hi)); return r;
}
__device__ __forceinline__ void fma2(ull& d, ull a, ull b) {
    asm("fma.rn.f32x2 %0, %1, %2, %3;" : "=l"(d) : "l"(a), "l"(b), "l"(d));
}
__device__ __forceinline__ void mul2(ull& d, ull a, ull b) {
    asm("mul.rn.f32x2 %0, %1, %2;" : "=l"(d) : "l"(a), "l"(b));
}
__device__ __forceinline__ float2 unpack2(ull v) {
    float lo, hi; asm("mov.b64 {%0,%1}, %2;" : "=f"(lo), "=f"(hi) : "l"(v));
    return make_float2(lo, hi);
}

// ---- bf16 split helper: v = hi + lo with ~2^-16 combined relative residual
__device__ __forceinline__ void split1(float v, __nv_bfloat16& h, __nv_bfloat16& l) {
    h = __float2bfloat16(v);
    l = __float2bfloat16(v - __bfloat162float(h));
}

// ---- scratch (device globals: allocation-free rule; device-side refs only)
__device__ float g_q[(size_t)MTOT * DMODEL];
__device__ float g_k[(size_t)MTOT * DMODEL];
__device__ float g_v[(size_t)MTOT * DMODEL];
__device__ float g_z[(size_t)MTOT * DMODEL];

__device__ __nv_bfloat16 gx_hi[(size_t)MTOT * DMODEL];
__device__ __nv_bfloat16 gx_lo[(size_t)MTOT * DMODEL];
__device__ __nv_bfloat16 gz_hi[(size_t)MTOT * DMODEL];
__device__ __nv_bfloat16 gz_lo[(size_t)MTOT * DMODEL];
// QKV weights, transposed per head: [which][h][n(128)][k(2048)]
__device__ __nv_bfloat16 gw_hi[(size_t)3 * NHEADS * DHEAD * DMODEL];
__device__ __nv_bfloat16 gw_lo[(size_t)3 * NHEADS * DHEAD * DMODEL];
// W_O transposed: [n(2048)][k(2048)]
__device__ __nv_bfloat16 gwo_hi[(size_t)DMODEL * DMODEL];
__device__ __nv_bfloat16 gwo_lo[(size_t)DMODEL * DMODEL];

// ---------------------------------------------------------------------------
// Prep kernels: split inputs into bf16 hi/lo (and transpose weights).
// ---------------------------------------------------------------------------
__global__ void __launch_bounds__(256) split_x_kernel(const float* __restrict__ x)
{
    size_t i = (size_t)blockIdx.x * blockDim.x + threadIdx.x;   // pair index
    float2 v = ((const float2*)x)[i];
    __nv_bfloat16 h0, l0, h1, l1;
    split1(v.x, h0, l0); split1(v.y, h1, l1);
    __nv_bfloat162 hp; hp.x = h0; hp.y = h1;
    __nv_bfloat162 lp; lp.x = l0; lp.y = l1;
    ((__nv_bfloat162*)gx_hi)[i] = hp;
    ((__nv_bfloat162*)gx_lo)[i] = lp;
}

__global__ void __launch_bounds__(256) split_z_kernel()
{
    size_t i = (size_t)blockIdx.x * blockDim.x + threadIdx.x;
    float2 v = ((const float2*)g_z)[i];
    __nv_bfloat16 h0, l0, h1, l1;
    split1(v.x, h0, l0); split1(v.y, h1, l1);
    __nv_bfloat162 hp; hp.x = h0; hp.y = h1;
    __nv_bfloat162 lp; lp.x = l0; lp.y = l1;
    ((__nv_bfloat162*)gz_hi)[i] = hp;
    ((__nv_bfloat162*)gz_lo)[i] = lp;
}

// W[h][k][n] -> gw[(which,h)][n][k], split hi/lo. grid (64, 4, 48), block (32,8).
__global__ void split_w_kernel(const float* __restrict__ Wq,
                               const float* __restrict__ Wk,
                               const float* __restrict__ Wv)
{
    const int which = blockIdx.z / NHEADS;
    const int h     = blockIdx.z % NHEADS;
    const float* W = ((which == 0) ? Wq : (which == 1) ? Wk : Wv)
                     + (size_t)h * DMODEL * DHEAD;
    const int k0 = blockIdx.x * 32;
    const int n0 = blockIdx.y * 32;

    __shared__ float tile[32][33];
    const int tx = threadIdx.x, ty = threadIdx.y;
#pragma unroll
    for (int r = 0; r < 4; r++)
        tile[ty + 8 * r][tx] = W[(size_t)(k0 + ty + 8 * r) * DHEAD + n0 + tx];
    __syncthreads();
    const size_t base = ((size_t)(which * NHEADS + h) * DHEAD);
#pragma unroll
    for (int r = 0; r < 4; r++) {
        float v = tile[tx][ty + 8 * r];
        __nv_bfloat16 hh, ll; split1(v, hh, ll);
        size_t idx = (base + n0 + ty + 8 * r) * DMODEL + k0 + tx;
        gw_hi[idx] = hh; gw_lo[idx] = ll;
    }
}

// Wo[k][n] -> gwo[n][k]. grid (64, 64), block (32,8).
__global__ void split_wo_kernel(const float* __restrict__ Wo)
{
    const int k0 = blockIdx.x * 32;
    const int n0 = blockIdx.y * 32;
    __shared__ float tile[32][33];
    const int tx = threadIdx.x, ty = threadIdx.y;
#pragma unroll
    for (int r = 0; r < 4; r++)
        tile[ty + 8 * r][tx] = Wo[(size_t)(k0 + ty + 8 * r) * DMODEL + n0 + tx];
    __syncthreads();
#pragma unroll
    for (int r = 0; r < 4; r++) {
        float v = tile[tx][ty + 8 * r];
        __nv_bfloat16 hh, ll; split1(v, hh, ll);
        size_t idx = (size_t)(n0 + ty + 8 * r) * DMODEL + k0 + tx;
        gwo_hi[idx] = hh; gwo_lo[idx] = ll;
    }
}

// ---------------------------------------------------------------------------
// bf16 split-GEMM core (mma.sync m16n8k16, 3-term error compensation).
// Block: 256 thr (8 warps, 4x2), tile 128(m) x 128(n), K step 32.
// A: row-major [m][k] bf16 hi/lo.  B: [n][k] bf16 hi/lo (pre-transposed).
// ---------------------------------------------------------------------------
#define KC   32
#define SSTR 40   // smem row stride in elements (80B; 8B-aligned copies)

#define MMA_BF16(c, a, b) \
    asm volatile("mma.sync.aligned.m16n8k16.row.col.f32.bf16.bf16.f32 " \
        "{%0,%1,%2,%3}, {%4,%5,%6,%7}, {%8,%9}, {%0,%1,%2,%3};" \
        : "+f"((c)[0]), "+f"((c)[1]), "+f"((c)[2]), "+f"((c)[3]) \
        : "r"((a)[0]), "r"((a)[1]), "r"((a)[2]), "r"((a)[3]), \
          "r"((b)[0]), "r"((b)[1]))

__device__ __forceinline__ void gemm_split_tile(
    const __nv_bfloat16* __restrict__ Ah, const __nv_bfloat16* __restrict__ Al,
    const __nv_bfloat16* __restrict__ Bh, const __nv_bfloat16* __restrict__ Bl,
    int mBase,           // A row offset of this block tile
    float* __restrict__ outBase,   // &out[mBase*ldo + colBase]
    size_t ldo,
    const float* __restrict__ bias)  // bias[col] for col in 0..127 of this tile
{
    __shared__ __nv_bfloat16 sAh[128 * SSTR], sAl[128 * SSTR];
    __shared__ __nv_bfloat16 sBh[128 * SSTR], sBl[128 * SSTR];

    const int tid  = threadIdx.x;
    const int wid  = tid >> 5;
    const int lane = tid & 31;
    const int wm = (wid & 3) * 32;    // warp m offset in tile
    const int wn = (wid >> 2) * 64;   // warp n offset in tile
    const int g = lane >> 2;          // group id 0..7
    const int t = lane & 3;           // thread-in-group

    float acc[2][8][4];
#pragma unroll
    for (int am = 0; am < 2; am++)
#pragma unroll
        for (int an = 0; an < 8; an++)
#pragma unroll
            for (int c = 0; c < 4; c++) acc[am][an][c] = 0.f;

    for (int k0 = 0; k0 < DMODEL; k0 += KC) {
        __syncthreads();
        // stage tiles: 128 rows x 32 bf16 = 1024 x 8B chunks per array
        for (int idx = tid; idx < 1024; idx += 256) {
            const int r = idx >> 3;          // row
            const int c = idx & 7;           // 8B chunk (4 bf16)
            const size_t go = (size_t)r * DMODEL + k0 + c * 4;
            *(uint2*)&sAh[r * SSTR + c * 4] = *(const uint2*)&Ah[(size_t)(mBase + r) * DMODEL + k0 + c * 4];
            *(uint2*)&sAl[r * SSTR + c * 4] = *(const uint2*)&Al[(size_t)(mBase + r) * DMODEL + k0 + c * 4];
            *(uint2*)&sBh[r * SSTR + c * 4] = *(const uint2*)&Bh[go];
            *(uint2*)&sBl[r * SSTR + c * 4] = *(const uint2*)&Bl[go];
        }
        __syncthreads();

#pragma unroll
        for (int ks = 0; ks < KC; ks += 16) {
            u32 afh[2][4], afl[2][4];
#pragma unroll
            for (int am = 0; am < 2; am++) {
                const int r0 = wm + am * 16 + g;
                afh[am][0] = *(const u32*)&sAh[(r0    ) * SSTR + ks + 2 * t];
                afh[am][1] = *(const u32*)&sAh[(r0 + 8) * SSTR + ks + 2 * t];
                afh[am][2] = *(const u32*)&sAh[(r0    ) * SSTR + ks + 2 * t + 8];
                afh[am][3] = *(const u32*)&sAh[(r0 + 8) * SSTR + ks + 2 * t + 8];
                afl[am][0] = *(const u32*)&sAl[(r0    ) * SSTR + ks + 2 * t];
                afl[am][1] = *(const u32*)&sAl[(r0 + 8) * SSTR + ks + 2 * t];
                afl[am][2] = *(const u32*)&sAl[(r0    ) * SSTR + ks + 2 * t + 8];
                afl[am][3] = *(const u32*)&sAl[(r0 + 8) * SSTR + ks + 2 * t + 8];
            }
            u32 bfh[8][2], bfl[8][2];
#pragma unroll
            for (int an = 0; an < 8; an++) {
                const int n = wn + an * 8 + g;
                bfh[an][0] = *(const u32*)&sBh[n * SSTR + ks + 2 * t];
                bfh[an][1] = *(const u32*)&sBh[n * SSTR + ks + 2 * t + 8];
                bfl[an][0] = *(const u32*)&sBl[n * SSTR + ks + 2 * t];
                bfl[an][1] = *(const u32*)&sBl[n * SSTR + ks + 2 * t + 8];
            }
#pragma unroll
            for (int am = 0; am < 2; am++)
#pragma unroll
                for (int an = 0; an < 8; an++) {
                    MMA_BF16(acc[am][an], afh[am], bfh[an]);
                    MMA_BF16(acc[am][an], afh[am], bfl[an]);
                    MMA_BF16(acc[am][an], afl[am], bfh[an]);
                }
        }
    }

    // epilogue: D[g][2t],D[g][2t+1],D[g+8][2t],D[g+8][2t+1]
#pragma unroll
    for (int am = 0; am < 2; am++)
#pragma unroll
        for (int an = 0; an < 8; an++) {
            const int col = wn + an * 8 + 2 * t;
            const int r0 = wm + am * 16 + g;
            float b0 = bias[col], b1 = bias[col + 1];
            outBase[(size_t)r0 * ldo + col]         = acc[am][an][0] + b0;
            outBase[(size_t)r0 * ldo + col + 1]     = acc[am][an][1] + b1;
            outBase[(size_t)(r0 + 8) * ldo + col]     = acc[am][an][2] + b0;
            outBase[(size_t)(r0 + 8) * ldo + col + 1] = acc[am][an][3] + b1;
        }
}

// QKV: grid (M/128, NHEADS, 3), block 256
__global__ void __launch_bounds__(256) qkv_mma_kernel(
    const float* __restrict__ bQ, const float* __restrict__ bK, const float* __restrict__ bV)
{
    const int mBase = blockIdx.x * 128;
    const int h     = blockIdx.y;
    const int which = blockIdx.z;
    const float* bias = ((which == 0) ? bQ : (which == 1) ? bK : bV) + h * DHEAD;
    float* out = (which == 0) ? g_q : (which == 1) ? g_k : g_v;
    const __nv_bfloat16* Bh = gw_hi + (size_t)(which * NHEADS + h) * DHEAD * DMODEL;
    const __nv_bfloat16* Bl = gw_lo + (size_t)(which * NHEADS + h) * DHEAD * DMODEL;
    gemm_split_tile(gx_hi, gx_lo, Bh, Bl, mBase,
                    out + (size_t)mBase * DMODEL + h * DHEAD, DMODEL, bias);
}

// out proj: grid (M/128, DMODEL/128), block 256
__global__ void __launch_bounds__(256) out_mma_kernel(
    const float* __restrict__ bO, float* __restrict__ out)
{
    const int mBase = blockIdx.x * 128;
    const int nBase = blockIdx.y * 128;
    gemm_split_tile(gz_hi, gz_lo,
                    gwo_hi + (size_t)nBase * DMODEL, gwo_lo + (size_t)nBase * DMODEL,
                    mBase, out + (size_t)mBase * DMODEL + nBase, DMODEL, bO + nBase);
}

// ---------------------------------------------------------------------------
// Fused causal attention (flash-style, fp32) — unchanged from R3.
// grid = (SEQLEN/64, NHEADS, BATCH), block = 256.
// ---------------------------------------------------------------------------
#define QPAD 132
#define PPAD 68

__global__ void __launch_bounds__(256) attn_kernel()
{
    const int qt = blockIdx.x;
    const int h  = blockIdx.y;
    const int b  = blockIdx.z;
    const int qBase = qt * 64;

    extern __shared__ float sm[];
    float* Qs  = sm;
    float* Ks  = Qs + 64 * QPAD;
    float* Vs  = Ks + 64 * QPAD;
    float* Ps  = Vs + 64 * QPAD;
    float* Red = Ps + 64 * PPAD;

    const int tid = threadIdx.x;
    const int tx = tid & 15;
    const int ty = tid >> 4;

    const float scale = 0.08838834764831845f;

    {
        const size_t baseQ = ((size_t)(b * SEQLEN + qBase) * NHEADS + h) * DHEAD;
        for (int i = tid; i < 64 * 32; i += 256) {
            int r = i >> 5, c4 = (i & 31) << 2;
            *(float4*)&Qs[r * QPAD + c4] =
                *(const float4*)&g_q[baseQ + (size_t)r * NHEADS * DHEAD + c4];
        }
    }

    float m_i[4], l_i[4];
    ull o2[4][8];
#pragma unroll
    for (int i = 0; i < 4; i++) {
        m_i[i] = NEG_BIG; l_i[i] = 0.f;
#pragma unroll
        for (int j = 0; j < 8; j++) o2[i][j] = 0ULL;
    }

    const int nkt = qt + 1;
    for (int kt = 0; kt < nkt; kt++) {
        const int kBase = kt * 64;
        __syncthreads();
        {
            const size_t baseK = ((size_t)(b * SEQLEN + kBase) * NHEADS + h) * DHEAD;
            for (int i = tid; i < 64 * 32; i += 256) {
                int r = i >> 5, c4 = (i & 31) << 2;
                size_t g = baseK + (size_t)r * NHEADS * DHEAD + c4;
                *(float4*)&Ks[r * QPAD + c4] = *(const float4*)&g_k[g];
                *(float4*)&Vs[r * QPAD + c4] = *(const float4*)&g_v[g];
            }
        }
        __syncthreads();

        ull s2[4][4];
#pragma unroll
        for (int i = 0; i < 4; i++)
#pragma unroll
            for (int j = 0; j < 4; j++) s2[i][j] = 0ULL;

#pragma unroll 4
        for (int e4 = 0; e4 < 32; e4++) {
            longlong2 a2[4], b2[4];
#pragma unroll
            for (int i = 0; i < 4; i++)
                a2[i] = *(const longlong2*)&Qs[(i * 16 + ty) * QPAD + e4 * 4];
#pragma unroll
            for (int j = 0; j < 4; j++)
                b2[j] = *(const longlong2*)&Ks[(j * 16 + tx) * QPAD + e4 * 4];
#pragma unroll
            for (int i = 0; i < 4; i++)
#pragma unroll
                for (int j = 0; j < 4; j++) {
                    fma2(s2[i][j], (ull)a2[i].x, (ull)b2[j].x);
                    fma2(s2[i][j], (ull)a2[i].y, (ull)b2[j].y);
                }
        }

        float s[4][4];
#pragma unroll
        for (int i = 0; i < 4; i++)
#pragma unroll
            for (int j = 0; j < 4; j++) {
                float2 v = unpack2(s2[i][j]);
                s[i][j] = v.x + v.y;
            }

#pragma unroll
        for (int i = 0; i < 4; i++) {
            const int qi = qBase + i * 16 + ty;
#pragma unroll
            for (int j = 0; j < 4; j++) {
                const int ki = kBase + j * 16 + tx;
                s[i][j] = (ki <= qi) ? s[i][j] * scale : NEG_BIG;
            }
        }

#pragma unroll
        for (int i = 0; i < 4; i++) {
            float mm = s[i][0];
#pragma unroll
            for (int j = 1; j < 4; j++) mm = fmaxf(mm, s[i][j]);
            Red[(i * 16 + ty) * 16 + tx] = mm;
        }
        __syncthreads();

        float mnew[4], alpha[4];
#pragma unroll
        for (int i = 0; i < 4; i++) {
            float mm = m_i[i];
            const int r = (i * 16 + ty) * 16;
#pragma unroll
            for (int t = 0; t < 16; t++) mm = fmaxf(mm, Red[r + t]);
            mnew[i] = mm;
            alpha[i] = __expf(m_i[i] - mm);
            m_i[i] = mm;
        }

        float p[4][4], ls[4];
#pragma unroll
        for (int i = 0; i < 4; i++) {
            float ssum = 0.f;
#pragma unroll
            for (int j = 0; j < 4; j++) {
                float pv = __expf(s[i][j] - mnew[i]);
                p[i][j] = pv;
                ssum += pv;
            }
            ls[i] = ssum;
        }
        __syncthreads();
#pragma unroll
        for (int i = 0; i < 4; i++) {
            Red[(i * 16 + ty) * 16 + tx] = ls[i];
#pragma unroll
            for (int j = 0; j < 4; j++)
                Ps[(i * 16 + ty) * PPAD + (j * 16 + tx)] = p[i][j];
        }
        __syncthreads();

#pragma unroll
        for (int i = 0; i < 4; i++) {
            float ssum = 0.f;
            const int r = (i * 16 + ty) * 16;
#pragma unroll
            for (int t = 0; t < 16; t++) ssum += Red[r + t];
            l_i[i] = l_i[i] * alpha[i] + ssum;
            ull al2 = pack2(alpha[i], alpha[i]);
#pragma unroll
            for (int j = 0; j < 8; j++) mul2(o2[i][j], o2[i][j], al2);
        }

#pragma unroll 2
        for (int jj = 0; jj < 64; jj += 2) {
            ull pa2[4], vb2[8];
#pragma unroll
            for (int i = 0; i < 4; i++)
                pa2[i] = *(const ull*)&Ps[(i * 16 + ty) * PPAD + jj];
#pragma unroll
            for (int j = 0; j < 8; j++)
                vb2[j] = pack2(Vs[jj * QPAD + j * 16 + tx],
                               Vs[(jj + 1) * QPAD + j * 16 + tx]);
#pragma unroll
            for (int i = 0; i < 4; i++)
#pragma unroll
                for (int j = 0; j < 8; j++)
                    fma2(o2[i][j], pa2[i], vb2[j]);
        }
    }

#pragma unroll
    for (int i = 0; i < 4; i++) {
        const size_t row = (size_t)(b * SEQLEN + qBase + i * 16 + ty);
        const float inv = 1.f / l_i[i];
#pragma unroll
        for (int j = 0; j < 8; j++) {
            float2 v = unpack2(o2[i][j]);
            g_z[(row * NHEADS + h) * DHEAD + j * 16 + tx] = (v.x + v.y) * inv;
        }
    }
}

// ---------------------------------------------------------------------------
// Launch
// ---------------------------------------------------------------------------
extern "C" void kernel_launch(void* const* d_in, const int* in_sizes, int n_in,
                              void* d_out, int out_size)
{
    const float* x  = (const float*)d_in[0];
    const float* Wq = (const float*)d_in[1];
    const float* Wk = (const float*)d_in[2];
    const float* Wv = (const float*)d_in[3];
    const float* Wo = (const float*)d_in[4];
    const float* bQ = (const float*)d_in[5];
    const float* bK = (const float*)d_in[6];
    const float* bV = (const float*)d_in[7];
    const float* bO = (const float*)d_in[8];
    float* out = (float*)d_out;

    // 0) split/transposes
    split_x_kernel<<<(MTOT * DMODEL / 2) / 256, 256>>>(x);
    split_w_kernel<<<dim3(DMODEL / 32, DHEAD / 32, 3 * NHEADS), dim3(32, 8)>>>(Wq, Wk, Wv);
    split_wo_kernel<<<dim3(DMODEL / 32, DMODEL / 32), dim3(32, 8)>>>(Wo);

    // 1) QKV projections (tensor cores, bf16 split)
    qkv_mma_kernel<<<dim3(MTOT / 128, NHEADS, 3), 256>>>(bQ, bK, bV);

    // 2) fused causal attention (fp32)
    const int smem_bytes = (3 * 64 * QPAD + 64 * PPAD + 64 * 16) * (int)sizeof(float);
    static bool attr_set = false;
    if (!attr_set) {
        cudaFuncSetAttribute(attn_kernel, cudaFuncAttributeMaxDynamicSharedMemorySize, smem_bytes);
        attr_set = true;
    }
    attn_kernel<<<dim3(SEQLEN / 64, NHEADS, BATCH), 256, smem_bytes>>>();

    // 3) output projection (tensor cores, bf16 split)
    split_z_kernel<<<(MTOT * DMODEL / 2) / 256, 256>>>();
    out_mma_kernel<<<dim3(MTOT / 128, DMODEL / 128), 256>>>(bO, out);

    (void)in_sizes; (void)n_in; (void)out_size;
}

// round 5
// speedup vs baseline: 2.1917x; 1.4624x over previous
#include <cuda_runtime.h>
#include <cuda_bf16.h>
#include <math.h>

// Problem constants
#define BATCH   2
#define SEQLEN  2048
#define DMODEL  2048
#define NHEADS  16
#define DHEAD   128
#define MTOT    (BATCH * SEQLEN)      // 4096

typedef unsigned int u32;
typedef unsigned short u16;

// ---- bf16 split helper: v = hi + lo with ~2^-16 combined relative residual
__device__ __forceinline__ void split1(float v, __nv_bfloat16& h, __nv_bfloat16& l) {
    h = __float2bfloat16(v);
    l = __float2bfloat16(v - __bfloat162float(h));
}
// pack two floats as bf16x2 (lo = first element convention, little-endian)
__device__ __forceinline__ u32 pack2bf(float lo, float hi) {
    u32 r; asm("cvt.rn.bf16x2.f32 %0, %1, %2;" : "=r"(r) : "f"(hi), "f"(lo)); return r;
}
__device__ __forceinline__ float ex2f(float x) {
    float y; asm("ex2.approx.f32 %0, %1;" : "=f"(y) : "f"(x)); return y;
}

// ---- scratch (device globals: allocation-free rule; device-side refs only)
__device__ __nv_bfloat16 gx_hi[(size_t)MTOT * DMODEL];
__device__ __nv_bfloat16 gx_lo[(size_t)MTOT * DMODEL];
// q,k,v split, layout [b][h][s][d]
__device__ __nv_bfloat16 gq_hi[(size_t)MTOT * DMODEL];
__device__ __nv_bfloat16 gq_lo[(size_t)MTOT * DMODEL];
__device__ __nv_bfloat16 gk_hi[(size_t)MTOT * DMODEL];
__device__ __nv_bfloat16 gk_lo[(size_t)MTOT * DMODEL];
__device__ __nv_bfloat16 gv_hi[(size_t)MTOT * DMODEL];
__device__ __nv_bfloat16 gv_lo[(size_t)MTOT * DMODEL];
// z split, layout [b*s][h*d]
__device__ __nv_bfloat16 gz_hi[(size_t)MTOT * DMODEL];
__device__ __nv_bfloat16 gz_lo[(size_t)MTOT * DMODEL];
// QKV weights, transposed per head: [which][h][n(128)][k(2048)]
__device__ __nv_bfloat16 gw_hi[(size_t)3 * NHEADS * DHEAD * DMODEL];
__device__ __nv_bfloat16 gw_lo[(size_t)3 * NHEADS * DHEAD * DMODEL];
// W_O transposed: [n(2048)][k(2048)]
__device__ __nv_bfloat16 gwo_hi[(size_t)DMODEL * DMODEL];
__device__ __nv_bfloat16 gwo_lo[(size_t)DMODEL * DMODEL];

// ---------------------------------------------------------------------------
// Prep kernels
// ---------------------------------------------------------------------------
__global__ void __launch_bounds__(256) split_x_kernel(const float* __restrict__ x)
{
    size_t i = (size_t)blockIdx.x * blockDim.x + threadIdx.x;   // pair index
    float2 v = ((const float2*)x)[i];
    __nv_bfloat16 h0, l0, h1, l1;
    split1(v.x, h0, l0); split1(v.y, h1, l1);
    __nv_bfloat162 hp; hp.x = h0; hp.y = h1;
    __nv_bfloat162 lp; lp.x = l0; lp.y = l1;
    ((__nv_bfloat162*)gx_hi)[i] = hp;
    ((__nv_bfloat162*)gx_lo)[i] = lp;
}

// W[h][k][n] -> gw[(which,h)][n][k], split hi/lo. grid (64, 4, 48), block (32,8).
__global__ void split_w_kernel(const float* __restrict__ Wq,
                               const float* __restrict__ Wk,
                               const float* __restrict__ Wv)
{
    const int which = blockIdx.z / NHEADS;
    const int h     = blockIdx.z % NHEADS;
    const float* W = ((which == 0) ? Wq : (which == 1) ? Wk : Wv)
                     + (size_t)h * DMODEL * DHEAD;
    const int k0 = blockIdx.x * 32;
    const int n0 = blockIdx.y * 32;

    __shared__ float tile[32][33];
    const int tx = threadIdx.x, ty = threadIdx.y;
#pragma unroll
    for (int r = 0; r < 4; r++)
        tile[ty + 8 * r][tx] = W[(size_t)(k0 + ty + 8 * r) * DHEAD + n0 + tx];
    __syncthreads();
    const size_t base = ((size_t)(which * NHEADS + h) * DHEAD);
#pragma unroll
    for (int r = 0; r < 4; r++) {
        float v = tile[tx][ty + 8 * r];
        __nv_bfloat16 hh, ll; split1(v, hh, ll);
        size_t idx = (base + n0 + ty + 8 * r) * DMODEL + k0 + tx;
        gw_hi[idx] = hh; gw_lo[idx] = ll;
    }
}

// Wo[k][n] -> gwo[n][k]. grid (64, 64), block (32,8).
__global__ void split_wo_kernel(const float* __restrict__ Wo)
{
    const int k0 = blockIdx.x * 32;
    const int n0 = blockIdx.y * 32;
    __shared__ float tile[32][33];
    const int tx = threadIdx.x, ty = threadIdx.y;
#pragma unroll
    for (int r = 0; r < 4; r++)
        tile[ty + 8 * r][tx] = Wo[(size_t)(k0 + ty + 8 * r) * DMODEL + n0 + tx];
    __syncthreads();
#pragma unroll
    for (int r = 0; r < 4; r++) {
        float v = tile[tx][ty + 8 * r];
        __nv_bfloat16 hh, ll; split1(v, hh, ll);
        size_t idx = (size_t)(n0 + ty + 8 * r) * DMODEL + k0 + tx;
        gwo_hi[idx] = hh; gwo_lo[idx] = ll;
    }
}

// ---------------------------------------------------------------------------
// bf16 split-GEMM core (mma.sync m16n8k16, 3-term error compensation).
// Block: 256 thr (8 warps, 4x2), tile 128(m) x 128(n), K step 32.
// ---------------------------------------------------------------------------
#define KC   32
#define SSTR 40

#define MMA_BF16(c, a, b) \
    asm volatile("mma.sync.aligned.m16n8k16.row.col.f32.bf16.bf16.f32 " \
        "{%0,%1,%2,%3}, {%4,%5,%6,%7}, {%8,%9}, {%0,%1,%2,%3};" \
        : "+f"((c)[0]), "+f"((c)[1]), "+f"((c)[2]), "+f"((c)[3]) \
        : "r"((a)[0]), "r"((a)[1]), "r"((a)[2]), "r"((a)[3]), \
          "r"((b)[0]), "r"((b)[1]))

__device__ __forceinline__ void gemm_split_core(
    const __nv_bfloat16* __restrict__ Ah, const __nv_bfloat16* __restrict__ Al,
    const __nv_bfloat16* __restrict__ Bh, const __nv_bfloat16* __restrict__ Bl,
    int mBase, float acc[2][8][4])
{
    __shared__ __nv_bfloat16 sAh[128 * SSTR], sAl[128 * SSTR];
    __shared__ __nv_bfloat16 sBh[128 * SSTR], sBl[128 * SSTR];

    const int tid  = threadIdx.x;
    const int wid  = tid >> 5;
    const int lane = tid & 31;
    const int wm = (wid & 3) * 32;
    const int wn = (wid >> 2) * 64;
    const int g = lane >> 2;
    const int t = lane & 3;

#pragma unroll
    for (int am = 0; am < 2; am++)
#pragma unroll
        for (int an = 0; an < 8; an++)
#pragma unroll
            for (int c = 0; c < 4; c++) acc[am][an][c] = 0.f;

    for (int k0 = 0; k0 < DMODEL; k0 += KC) {
        __syncthreads();
        for (int idx = tid; idx < 1024; idx += 256) {
            const int r = idx >> 3;
            const int c = idx & 7;
            const size_t go = (size_t)r * DMODEL + k0 + c * 4;
            *(uint2*)&sAh[r * SSTR + c * 4] = *(const uint2*)&Ah[(size_t)(mBase + r) * DMODEL + k0 + c * 4];
            *(uint2*)&sAl[r * SSTR + c * 4] = *(const uint2*)&Al[(size_t)(mBase + r) * DMODEL + k0 + c * 4];
            *(uint2*)&sBh[r * SSTR + c * 4] = *(const uint2*)&Bh[go];
            *(uint2*)&sBl[r * SSTR + c * 4] = *(const uint2*)&Bl[go];
        }
        __syncthreads();

#pragma unroll
        for (int ks = 0; ks < KC; ks += 16) {
            u32 afh[2][4], afl[2][4];
#pragma unroll
            for (int am = 0; am < 2; am++) {
                const int r0 = wm + am * 16 + g;
                afh[am][0] = *(const u32*)&sAh[(r0    ) * SSTR + ks + 2 * t];
                afh[am][1] = *(const u32*)&sAh[(r0 + 8) * SSTR + ks + 2 * t];
                afh[am][2] = *(const u32*)&sAh[(r0    ) * SSTR + ks + 2 * t + 8];
                afh[am][3] = *(const u32*)&sAh[(r0 + 8) * SSTR + ks + 2 * t + 8];
                afl[am][0] = *(const u32*)&sAl[(r0    ) * SSTR + ks + 2 * t];
                afl[am][1] = *(const u32*)&sAl[(r0 + 8) * SSTR + ks + 2 * t];
                afl[am][2] = *(const u32*)&sAl[(r0    ) * SSTR + ks + 2 * t + 8];
                afl[am][3] = *(const u32*)&sAl[(r0 + 8) * SSTR + ks + 2 * t + 8];
            }
            u32 bfh[8][2], bfl[8][2];
#pragma unroll
            for (int an = 0; an < 8; an++) {
                const int n = wn + an * 8 + g;
                bfh[an][0] = *(const u32*)&sBh[n * SSTR + ks + 2 * t];
                bfh[an][1] = *(const u32*)&sBh[n * SSTR + ks + 2 * t + 8];
                bfl[an][0] = *(const u32*)&sBl[n * SSTR + ks + 2 * t];
                bfl[an][1] = *(const u32*)&sBl[n * SSTR + ks + 2 * t + 8];
            }
#pragma unroll
            for (int am = 0; am < 2; am++)
#pragma unroll
                for (int an = 0; an < 8; an++) {
                    MMA_BF16(acc[am][an], afh[am], bfh[an]);
                    MMA_BF16(acc[am][an], afh[am], bfl[an]);
                    MMA_BF16(acc[am][an], afl[am], bfh[an]);
                }
        }
    }
}

// QKV: grid (M/128, NHEADS, 3), block 256. Writes split q/k/v in [b,h,s,d].
__global__ void __launch_bounds__(256) qkv_mma_kernel(
    const float* __restrict__ bQ, const float* __restrict__ bK, const float* __restrict__ bV)
{
    const int mBase = blockIdx.x * 128;
    const int h     = blockIdx.y;
    const int which = blockIdx.z;
    const float* bias = ((which == 0) ? bQ : (which == 1) ? bK : bV) + h * DHEAD;
    __nv_bfloat16* dhi = (which == 0) ? gq_hi : (which == 1) ? gk_hi : gv_hi;
    __nv_bfloat16* dlo = (which == 0) ? gq_lo : (which == 1) ? gk_lo : gv_lo;
    const __nv_bfloat16* Bh = gw_hi + (size_t)(which * NHEADS + h) * DHEAD * DMODEL;
    const __nv_bfloat16* Bl = gw_lo + (size_t)(which * NHEADS + h) * DHEAD * DMODEL;

    float acc[2][8][4];
    gemm_split_core(gx_hi, gx_lo, Bh, Bl, mBase, acc);

    const int tid = threadIdx.x, wid = tid >> 5, lane = tid & 31;
    const int wm = (wid & 3) * 32, wn = (wid >> 2) * 64;
    const int g = lane >> 2, t = lane & 3;

#pragma unroll
    for (int am = 0; am < 2; am++)
#pragma unroll
        for (int an = 0; an < 8; an++) {
            const int col = wn + an * 8 + 2 * t;   // d index, even
            const float b0 = bias[col], b1 = bias[col + 1];
#pragma unroll
            for (int half = 0; half < 2; half++) {
                const int m = mBase + wm + am * 16 + g + 8 * half;   // global row
                const int bb = m >> 11;            // batch (SEQLEN=2048)
                const int s  = m & (SEQLEN - 1);
                const size_t dst = (((size_t)(bb * NHEADS + h) * SEQLEN + s) * DHEAD + col);
                float v0 = acc[am][an][2 * half + 0] + b0;
                float v1 = acc[am][an][2 * half + 1] + b1;
                __nv_bfloat16 h0, l0, h1, l1;
                split1(v0, h0, l0); split1(v1, h1, l1);
                __nv_bfloat162 hp; hp.x = h0; hp.y = h1;
                __nv_bfloat162 lp; lp.x = l0; lp.y = l1;
                *(__nv_bfloat162*)&dhi[dst] = hp;
                *(__nv_bfloat162*)&dlo[dst] = lp;
            }
        }
}

// out proj: grid (M/128, DMODEL/128), block 256
__global__ void __launch_bounds__(256) out_mma_kernel(
    const float* __restrict__ bO, float* __restrict__ out)
{
    const int mBase = blockIdx.x * 128;
    const int nBase = blockIdx.y * 128;
    float acc[2][8][4];
    gemm_split_core(gz_hi, gz_lo,
                    gwo_hi + (size_t)nBase * DMODEL, gwo_lo + (size_t)nBase * DMODEL,
                    mBase, acc);

    const int tid = threadIdx.x, wid = tid >> 5, lane = tid & 31;
    const int wm = (wid & 3) * 32, wn = (wid >> 2) * 64;
    const int g = lane >> 2, t = lane & 3;
    float* outBase = out + (size_t)mBase * DMODEL + nBase;
#pragma unroll
    for (int am = 0; am < 2; am++)
#pragma unroll
        for (int an = 0; an < 8; an++) {
            const int col = wn + an * 8 + 2 * t;
            const int r0 = wm + am * 16 + g;
            float b0 = bO[nBase + col], b1 = bO[nBase + col + 1];
            outBase[(size_t)r0 * DMODEL + col]           = acc[am][an][0] + b0;
            outBase[(size_t)r0 * DMODEL + col + 1]       = acc[am][an][1] + b1;
            outBase[(size_t)(r0 + 8) * DMODEL + col]     = acc[am][an][2] + b0;
            outBase[(size_t)(r0 + 8) * DMODEL + col + 1] = acc[am][an][3] + b1;
        }
}

// ---------------------------------------------------------------------------
// Tensor-core flash attention.
// grid = (SEQLEN/128, NHEADS, BATCH), block = 256 (8 warps).
// Q tile 128 rows (warp w: rows 16w..16w+15), K/V tiles 64.
// All mma m16n8k16 bf16 with 3-term hi/lo split (S and PV).
// ---------------------------------------------------------------------------
#define ASTR 136   // bf16 row stride (272B, 16B-aligned)

__global__ void __launch_bounds__(256, 1) attn_mma_kernel()
{
    const int qt = gridDim.x - 1 - blockIdx.x;   // heavy tiles first
    const int h  = blockIdx.y;
    const int b  = blockIdx.z;
    const int qBase = qt * 128;

    extern __shared__ __nv_bfloat16 smem_bf[];
    __nv_bfloat16* sQh = smem_bf;                 // [128][ASTR]
    __nv_bfloat16* sQl = sQh + 128 * ASTR;
    __nv_bfloat16* sKh = sQl + 128 * ASTR;        // [64][ASTR]
    __nv_bfloat16* sKl = sKh + 64 * ASTR;
    __nv_bfloat16* sVh = sKl + 64 * ASTR;         // [64][ASTR]
    __nv_bfloat16* sVl = sVh + 64 * ASTR;

    const int tid = threadIdx.x;
    const int wid = tid >> 5;
    const int lane = tid & 31;
    const int g = lane >> 2;
    const int t = lane & 3;
    const int wrow = wid * 16;

    const size_t bh = (size_t)(b * NHEADS + h) * SEQLEN * DHEAD;
    const __nv_bfloat16* qh = gq_hi + bh;
    const __nv_bfloat16* ql = gq_lo + bh;
    const __nv_bfloat16* kh = gk_hi + bh;
    const __nv_bfloat16* kl = gk_lo + bh;
    const __nv_bfloat16* vh = gv_hi + bh;
    const __nv_bfloat16* vl = gv_lo + bh;

    // load Q tile (128 x 128 bf16, uint4 = 8 elems)
    for (int idx = tid; idx < 128 * 16; idx += 256) {
        const int r = idx >> 4, c8 = (idx & 15) * 8;
        *(uint4*)&sQh[r * ASTR + c8] = *(const uint4*)&qh[(size_t)(qBase + r) * DHEAD + c8];
        *(uint4*)&sQl[r * ASTR + c8] = *(const uint4*)&ql[(size_t)(qBase + r) * DHEAD + c8];
    }

    float o[16][4];
#pragma unroll
    for (int j = 0; j < 16; j++)
#pragma unroll
        for (int c = 0; c < 4; c++) o[j][c] = 0.f;
    float m0 = -1e30f, m1 = -1e30f, l0 = 0.f, l1 = 0.f;

    // scale folded into log2 domain: softmax(s/sqrt(d)) = 2^(s*sl2e - max)
    const float sl2e = 0.08838834764831845f * 1.4426950408889634f;

    const int nkt = 2 * qt + 2;
    for (int kt = 0; kt < nkt; kt++) {
        const int kBase = kt * 64;
        __syncthreads();
        for (int idx = tid; idx < 64 * 16; idx += 256) {
            const int r = idx >> 4, c8 = (idx & 15) * 8;
            const size_t gsrc = (size_t)(kBase + r) * DHEAD + c8;
            *(uint4*)&sKh[r * ASTR + c8] = *(const uint4*)&kh[gsrc];
            *(uint4*)&sKl[r * ASTR + c8] = *(const uint4*)&kl[gsrc];
            *(uint4*)&sVh[r * ASTR + c8] = *(const uint4*)&vh[gsrc];
            *(uint4*)&sVl[r * ASTR + c8] = *(const uint4*)&vl[gsrc];
        }
        __syncthreads();

        // warp fully masked? (all its rows < all tile cols)
        if (kBase > qBase + wrow + 15) continue;

        // ---- S = Q K^T (m16 x n64, k=128)
        float sacc[8][4];
#pragma unroll
        for (int an = 0; an < 8; an++)
#pragma unroll
            for (int c = 0; c < 4; c++) sacc[an][c] = 0.f;

#pragma unroll
        for (int ks = 0; ks < DHEAD; ks += 16) {
            u32 ah[4], al[4];
            const int r0 = wrow + g;
            ah[0] = *(const u32*)&sQh[(r0    ) * ASTR + ks + 2 * t];
            ah[1] = *(const u32*)&sQh[(r0 + 8) * ASTR + ks + 2 * t];
            ah[2] = *(const u32*)&sQh[(r0    ) * ASTR + ks + 2 * t + 8];
            ah[3] = *(const u32*)&sQh[(r0 + 8) * ASTR + ks + 2 * t + 8];
            al[0] = *(const u32*)&sQl[(r0    ) * ASTR + ks + 2 * t];
            al[1] = *(const u32*)&sQl[(r0 + 8) * ASTR + ks + 2 * t];
            al[2] = *(const u32*)&sQl[(r0    ) * ASTR + ks + 2 * t + 8];
            al[3] = *(const u32*)&sQl[(r0 + 8) * ASTR + ks + 2 * t + 8];
#pragma unroll
            for (int an = 0; an < 8; an++) {
                const int n = an * 8 + g;
                u32 bh2[2], bl2[2];
                bh2[0] = *(const u32*)&sKh[n * ASTR + ks + 2 * t];
                bh2[1] = *(const u32*)&sKh[n * ASTR + ks + 2 * t + 8];
                bl2[0] = *(const u32*)&sKl[n * ASTR + ks + 2 * t];
                bl2[1] = *(const u32*)&sKl[n * ASTR + ks + 2 * t + 8];
                MMA_BF16(sacc[an], ah, bh2);
                MMA_BF16(sacc[an], ah, bl2);
                MMA_BF16(sacc[an], al, bh2);
            }
        }

        // ---- scale to log2 domain + causal mask
        const int qr0 = qBase + wrow + g;
        const int qr1 = qr0 + 8;
#pragma unroll
        for (int an = 0; an < 8; an++) {
            const int c0 = kBase + an * 8 + 2 * t;
            sacc[an][0] = (c0     <= qr0) ? sacc[an][0] * sl2e : -1e30f;
            sacc[an][1] = (c0 + 1 <= qr0) ? sacc[an][1] * sl2e : -1e30f;
            sacc[an][2] = (c0     <= qr1) ? sacc[an][2] * sl2e : -1e30f;
            sacc[an][3] = (c0 + 1 <= qr1) ? sacc[an][3] * sl2e : -1e30f;
        }

        // ---- row max (local + quad reduce)
        float mx0 = -1e30f, mx1 = -1e30f;
#pragma unroll
        for (int an = 0; an < 8; an++) {
            mx0 = fmaxf(mx0, fmaxf(sacc[an][0], sacc[an][1]));
            mx1 = fmaxf(mx1, fmaxf(sacc[an][2], sacc[an][3]));
        }
        mx0 = fmaxf(mx0, __shfl_xor_sync(0xffffffffu, mx0, 1));
        mx0 = fmaxf(mx0, __shfl_xor_sync(0xffffffffu, mx0, 2));
        mx1 = fmaxf(mx1, __shfl_xor_sync(0xffffffffu, mx1, 1));
        mx1 = fmaxf(mx1, __shfl_xor_sync(0xffffffffu, mx1, 2));

        const float mn0 = fmaxf(m0, mx0), mn1 = fmaxf(m1, mx1);
        const float al0 = ex2f(m0 - mn0), al1 = ex2f(m1 - mn1);
        m0 = mn0; m1 = mn1;

        // ---- p = 2^(s - m), row sums
        float s0 = 0.f, s1 = 0.f;
#pragma unroll
        for (int an = 0; an < 8; an++) {
            sacc[an][0] = ex2f(sacc[an][0] - mn0);
            sacc[an][1] = ex2f(sacc[an][1] - mn0);
            sacc[an][2] = ex2f(sacc[an][2] - mn1);
            sacc[an][3] = ex2f(sacc[an][3] - mn1);
            s0 += sacc[an][0] + sacc[an][1];
            s1 += sacc[an][2] + sacc[an][3];
        }
        s0 += __shfl_xor_sync(0xffffffffu, s0, 1);
        s0 += __shfl_xor_sync(0xffffffffu, s0, 2);
        s1 += __shfl_xor_sync(0xffffffffu, s1, 1);
        s1 += __shfl_xor_sync(0xffffffffu, s1, 2);
        l0 = l0 * al0 + s0;
        l1 = l1 * al1 + s1;

        // ---- O *= alpha
#pragma unroll
        for (int j = 0; j < 16; j++) {
            o[j][0] *= al0; o[j][1] *= al0;
            o[j][2] *= al1; o[j][3] *= al1;
        }

        // ---- O += P V  (P from sacc: C-frag of ntiles 2jp,2jp+1 == A-frag of kstep jp)
        const u16* sVh16 = (const u16*)sVh;
        const u16* sVl16 = (const u16*)sVl;
#pragma unroll
        for (int jp = 0; jp < 4; jp++) {
            // split P values to hi/lo bf16 fragments
            u32 aph[4], apl[4];
            {
                float p00 = sacc[2 * jp][0],     p01 = sacc[2 * jp][1];
                float p02 = sacc[2 * jp][2],     p03 = sacc[2 * jp][3];
                float p10 = sacc[2 * jp + 1][0], p11 = sacc[2 * jp + 1][1];
                float p12 = sacc[2 * jp + 1][2], p13 = sacc[2 * jp + 1][3];
                __nv_bfloat16 hh, ll;
                float h00, h01, h02, h03, h10, h11, h12, h13;
                split1(p00, hh, ll); h00 = __bfloat162float(hh);
                split1(p01, hh, ll); h01 = __bfloat162float(hh);
                split1(p02, hh, ll); h02 = __bfloat162float(hh);
                split1(p03, hh, ll); h03 = __bfloat162float(hh);
                split1(p10, hh, ll); h10 = __bfloat162float(hh);
                split1(p11, hh, ll); h11 = __bfloat162float(hh);
                split1(p12, hh, ll); h12 = __bfloat162float(hh);
                split1(p13, hh, ll); h13 = __bfloat162float(hh);
                aph[0] = pack2bf(h00, h01);
                aph[1] = pack2bf(h02, h03);
                aph[2] = pack2bf(h10, h11);
                aph[3] = pack2bf(h12, h13);
                apl[0] = pack2bf(p00 - h00, p01 - h01);
                apl[1] = pack2bf(p02 - h02, p03 - h03);
                apl[2] = pack2bf(p10 - h10, p11 - h11);
                apl[3] = pack2bf(p12 - h12, p13 - h13);
            }
            const int ks = 16 * jp;
#pragma unroll
            for (int an = 0; an < 16; an++) {
                const int n = an * 8 + g;     // d index
                u32 bh2[2], bl2[2];
                {
                    u32 v0 = sVh16[(ks + 2 * t)     * ASTR + n];
                    u32 v1 = sVh16[(ks + 2 * t + 1) * ASTR + n];
                    u32 v8 = sVh16[(ks + 2 * t + 8) * ASTR + n];
                    u32 v9 = sVh16[(ks + 2 * t + 9) * ASTR + n];
                    bh2[0] = v0 | (v1 << 16);
                    bh2[1] = v8 | (v9 << 16);
                    v0 = sVl16[(ks + 2 * t)     * ASTR + n];
                    v1 = sVl16[(ks + 2 * t + 1) * ASTR + n];
                    v8 = sVl16[(ks + 2 * t + 8) * ASTR + n];
                    v9 = sVl16[(ks + 2 * t + 9) * ASTR + n];
                    bl2[0] = v0 | (v1 << 16);
                    bl2[1] = v8 | (v9 << 16);
                }
                MMA_BF16(o[an], aph, bh2);
                MMA_BF16(o[an], aph, bl2);
                MMA_BF16(o[an], apl, bh2);
            }
        }
    }

    // ---- epilogue: z = O / l, split to bf16 hi/lo, layout [b*s][h*128+d]
    const float inv0 = 1.f / l0;
    const float inv1 = 1.f / l1;
    const int r0 = qBase + wrow + g;
#pragma unroll
    for (int an = 0; an < 16; an++) {
        const int col = an * 8 + 2 * t;   // d, even
#pragma unroll
        for (int half = 0; half < 2; half++) {
            const int row = r0 + 8 * half;
            const float inv = half ? inv1 : inv0;
            float z0 = o[an][2 * half + 0] * inv;
            float z1 = o[an][2 * half + 1] * inv;
            __nv_bfloat16 h0, lo0, h1, lo1;
            split1(z0, h0, lo0); split1(z1, h1, lo1);
            __nv_bfloat162 hp; hp.x = h0; hp.y = h1;
            __nv_bfloat162 lp; lp.x = lo0; lp.y = lo1;
            const size_t dst = ((size_t)(b * SEQLEN + row) * DMODEL + h * DHEAD + col);
            *(__nv_bfloat162*)&gz_hi[dst] = hp;
            *(__nv_bfloat162*)&gz_lo[dst] = lp;
        }
    }
}

// ---------------------------------------------------------------------------
// Launch
// ---------------------------------------------------------------------------
extern "C" void kernel_launch(void* const* d_in, const int* in_sizes, int n_in,
                              void* d_out, int out_size)
{
    const float* x  = (const float*)d_in[0];
    const float* Wq = (const float*)d_in[1];
    const float* Wk = (const float*)d_in[2];
    const float* Wv = (const float*)d_in[3];
    const float* Wo = (const float*)d_in[4];
    const float* bQ = (const float*)d_in[5];
    const float* bK = (const float*)d_in[6];
    const float* bV = (const float*)d_in[7];
    const float* bO = (const float*)d_in[8];
    float* out = (float*)d_out;

    // 0) split/transposes
    split_x_kernel<<<(MTOT * DMODEL / 2) / 256, 256>>>(x);
    split_w_kernel<<<dim3(DMODEL / 32, DHEAD / 32, 3 * NHEADS), dim3(32, 8)>>>(Wq, Wk, Wv);
    split_wo_kernel<<<dim3(DMODEL / 32, DMODEL / 32), dim3(32, 8)>>>(Wo);

    // 1) QKV projections (tensor cores) -> split q/k/v [b,h,s,d]
    qkv_mma_kernel<<<dim3(MTOT / 128, NHEADS, 3), 256>>>(bQ, bK, bV);

    // 2) tensor-core flash attention -> split z
    const int attn_smem = (2 * 128 * ASTR + 4 * 64 * ASTR) * (int)sizeof(__nv_bfloat16);
    static bool attr_set = false;
    if (!attr_set) {
        cudaFuncSetAttribute(attn_mma_kernel, cudaFuncAttributeMaxDynamicSharedMemorySize, attn_smem);
        attr_set = true;
    }
    attn_mma_kernel<<<dim3(SEQLEN / 128, NHEADS, BATCH), 256, attn_smem>>>();

    // 3) output projection (tensor cores)
    out_mma_kernel<<<dim3(MTOT / 128, DMODEL / 128), 256>>>(bO, out);

    (void)in_sizes; (void)n_in; (void)out_size;
}

// round 6
// speedup vs baseline: 2.5932x; 1.1832x over previous
#include <cuda_runtime.h>
#include <cuda_bf16.h>
#include <math.h>

// Problem constants
#define BATCH   2
#define SEQLEN  2048
#define DMODEL  2048
#define NHEADS  16
#define DHEAD   128
#define MTOT    (BATCH * SEQLEN)      // 4096

typedef unsigned int u32;
typedef unsigned short u16;

// ---- bf16 split helper: v = hi + lo with ~2^-16 combined relative residual
__device__ __forceinline__ void split1(float v, __nv_bfloat16& h, __nv_bfloat16& l) {
    h = __float2bfloat16(v);
    l = __float2bfloat16(v - __bfloat162float(h));
}
__device__ __forceinline__ u32 pack2bf(float lo, float hi) {
    u32 r; asm("cvt.rn.bf16x2.f32 %0, %1, %2;" : "=r"(r) : "f"(hi), "f"(lo)); return r;
}
__device__ __forceinline__ float ex2f(float x) {
    float y; asm("ex2.approx.f32 %0, %1;" : "=f"(y) : "f"(x)); return y;
}
// ---- cp.async helpers (16B)
__device__ __forceinline__ void cpa16(u32 dst_smem, const void* src) {
    asm volatile("cp.async.cg.shared.global [%0], [%1], 16;" :: "r"(dst_smem), "l"(src));
}
#define CP_COMMIT() asm volatile("cp.async.commit_group;")
#define CP_WAIT1()  asm volatile("cp.async.wait_group 1;")
#define CP_WAIT0()  asm volatile("cp.async.wait_group 0;")

// ---- scratch (device globals; device-side refs only)
__device__ __nv_bfloat16 gx_hi[(size_t)MTOT * DMODEL];
__device__ __nv_bfloat16 gx_lo[(size_t)MTOT * DMODEL];
__device__ __nv_bfloat16 gq_hi[(size_t)MTOT * DMODEL];
__device__ __nv_bfloat16 gq_lo[(size_t)MTOT * DMODEL];
__device__ __nv_bfloat16 gk_hi[(size_t)MTOT * DMODEL];
__device__ __nv_bfloat16 gk_lo[(size_t)MTOT * DMODEL];
__device__ __nv_bfloat16 gv_hi[(size_t)MTOT * DMODEL];
__device__ __nv_bfloat16 gv_lo[(size_t)MTOT * DMODEL];
__device__ __nv_bfloat16 gz_hi[(size_t)MTOT * DMODEL];
__device__ __nv_bfloat16 gz_lo[(size_t)MTOT * DMODEL];
// QKV weights transposed per head: [which][h][n(128)][k(2048)]
__device__ __nv_bfloat16 gw_hi[(size_t)3 * NHEADS * DHEAD * DMODEL];
__device__ __nv_bfloat16 gw_lo[(size_t)3 * NHEADS * DHEAD * DMODEL];
// W_O transposed: [n(2048)][k(2048)]
__device__ __nv_bfloat16 gwo_hi[(size_t)DMODEL * DMODEL];
__device__ __nv_bfloat16 gwo_lo[(size_t)DMODEL * DMODEL];

// ---------------------------------------------------------------------------
// Prep kernels
// ---------------------------------------------------------------------------
__global__ void __launch_bounds__(256) split_x_kernel(const float* __restrict__ x)
{
    size_t i = (size_t)blockIdx.x * blockDim.x + threadIdx.x;
    float2 v = ((const float2*)x)[i];
    __nv_bfloat16 h0, l0, h1, l1;
    split1(v.x, h0, l0); split1(v.y, h1, l1);
    __nv_bfloat162 hp; hp.x = h0; hp.y = h1;
    __nv_bfloat162 lp; lp.x = l0; lp.y = l1;
    ((__nv_bfloat162*)gx_hi)[i] = hp;
    ((__nv_bfloat162*)gx_lo)[i] = lp;
}

__global__ void split_w_kernel(const float* __restrict__ Wq,
                               const float* __restrict__ Wk,
                               const float* __restrict__ Wv)
{
    const int which = blockIdx.z / NHEADS;
    const int h     = blockIdx.z % NHEADS;
    const float* W = ((which == 0) ? Wq : (which == 1) ? Wk : Wv)
                     + (size_t)h * DMODEL * DHEAD;
    const int k0 = blockIdx.x * 32;
    const int n0 = blockIdx.y * 32;

    __shared__ float tile[32][33];
    const int tx = threadIdx.x, ty = threadIdx.y;
#pragma unroll
    for (int r = 0; r < 4; r++)
        tile[ty + 8 * r][tx] = W[(size_t)(k0 + ty + 8 * r) * DHEAD + n0 + tx];
    __syncthreads();
    const size_t base = ((size_t)(which * NHEADS + h) * DHEAD);
#pragma unroll
    for (int r = 0; r < 4; r++) {
        float v = tile[tx][ty + 8 * r];
        __nv_bfloat16 hh, ll; split1(v, hh, ll);
        size_t idx = (base + n0 + ty + 8 * r) * DMODEL + k0 + tx;
        gw_hi[idx] = hh; gw_lo[idx] = ll;
    }
}

__global__ void split_wo_kernel(const float* __restrict__ Wo)
{
    const int k0 = blockIdx.x * 32;
    const int n0 = blockIdx.y * 32;
    __shared__ float tile[32][33];
    const int tx = threadIdx.x, ty = threadIdx.y;
#pragma unroll
    for (int r = 0; r < 4; r++)
        tile[ty + 8 * r][tx] = Wo[(size_t)(k0 + ty + 8 * r) * DMODEL + n0 + tx];
    __syncthreads();
#pragma unroll
    for (int r = 0; r < 4; r++) {
        float v = tile[tx][ty + 8 * r];
        __nv_bfloat16 hh, ll; split1(v, hh, ll);
        size_t idx = (size_t)(n0 + ty + 8 * r) * DMODEL + k0 + tx;
        gwo_hi[idx] = hh; gwo_lo[idx] = ll;
    }
}

// ---------------------------------------------------------------------------
// bf16 split-GEMM core (mma m16n8k16, 3-term), cp.async 2-stage pipeline.
// Block 256 thr (8 warps, 4x2), tile 128x128, K step 32.
// ---------------------------------------------------------------------------
#define KC   32
#define SSTR 40
#define GARR  (128 * SSTR)        // elems per array per stage
#define GSTAGE (4 * GARR)         // elems per stage
#define GEMM_SMEM (2 * GSTAGE * 2)  // bytes

#define MMA_BF16(c, a, b) \
    asm volatile("mma.sync.aligned.m16n8k16.row.col.f32.bf16.bf16.f32 " \
        "{%0,%1,%2,%3}, {%4,%5,%6,%7}, {%8,%9}, {%0,%1,%2,%3};" \
        : "+f"((c)[0]), "+f"((c)[1]), "+f"((c)[2]), "+f"((c)[3]) \
        : "r"((a)[0]), "r"((a)[1]), "r"((a)[2]), "r"((a)[3]), \
          "r"((b)[0]), "r"((b)[1]))

__device__ __forceinline__ void gemm_split_core(
    const __nv_bfloat16* __restrict__ Ah, const __nv_bfloat16* __restrict__ Al,
    const __nv_bfloat16* __restrict__ Bh, const __nv_bfloat16* __restrict__ Bl,
    int mBase, float acc[2][8][4], __nv_bfloat16* smem)
{
    const int tid  = threadIdx.x;
    const int wid  = tid >> 5;
    const int lane = tid & 31;
    const int wm = (wid & 3) * 32;
    const int wn = (wid >> 2) * 64;
    const int g = lane >> 2;
    const int t = lane & 3;

    const u32 sbase = (u32)__cvta_generic_to_shared(smem);

#pragma unroll
    for (int am = 0; am < 2; am++)
#pragma unroll
        for (int an = 0; an < 8; an++)
#pragma unroll
            for (int c = 0; c < 4; c++) acc[am][an][c] = 0.f;

    // issue one K-tile (4 arrays x 128 rows x 32 bf16 = 512 x 16B chunks each)
    auto issue_tile = [&](int k0, int st) {
        const u32 b0 = sbase + (u32)st * (GSTAGE * 2);
#pragma unroll
        for (int it = 0; it < 2; it++) {
            const int idx = tid + it * 256;      // 0..511
            const int r = idx >> 2;
            const int c = idx & 3;
            const u32 doff = (u32)(r * SSTR + c * 8) * 2;
            const size_t aoff = (size_t)(mBase + r) * DMODEL + k0 + c * 8;
            const size_t boff = (size_t)r * DMODEL + k0 + c * 8;
            cpa16(b0 + doff,                 Ah + aoff);
            cpa16(b0 + GARR * 2 + doff,      Al + aoff);
            cpa16(b0 + 2 * GARR * 2 + doff,  Bh + boff);
            cpa16(b0 + 3 * GARR * 2 + doff,  Bl + boff);
        }
        CP_COMMIT();
    };

    const int NKT = DMODEL / KC;   // 64
    issue_tile(0, 0);

    for (int kt = 0; kt < NKT; kt++) {
        const int cur = kt & 1;
        __syncthreads();   // compute(kt-1) on buf(1-cur) done -> safe to overwrite
        if (kt + 1 < NKT) {
            issue_tile((kt + 1) * KC, 1 - cur);
            CP_WAIT1();    // tile kt landed
        } else {
            CP_WAIT0();
        }
        __syncthreads();

        const __nv_bfloat16* sAh = smem + cur * GSTAGE;
        const __nv_bfloat16* sAl = sAh + GARR;
        const __nv_bfloat16* sBh = sAl + GARR;
        const __nv_bfloat16* sBl = sBh + GARR;

#pragma unroll
        for (int ks = 0; ks < KC; ks += 16) {
            u32 afh[2][4], afl[2][4];
#pragma unroll
            for (int am = 0; am < 2; am++) {
                const int r0 = wm + am * 16 + g;
                afh[am][0] = *(const u32*)&sAh[(r0    ) * SSTR + ks + 2 * t];
                afh[am][1] = *(const u32*)&sAh[(r0 + 8) * SSTR + ks + 2 * t];
                afh[am][2] = *(const u32*)&sAh[(r0    ) * SSTR + ks + 2 * t + 8];
                afh[am][3] = *(const u32*)&sAh[(r0 + 8) * SSTR + ks + 2 * t + 8];
                afl[am][0] = *(const u32*)&sAl[(r0    ) * SSTR + ks + 2 * t];
                afl[am][1] = *(const u32*)&sAl[(r0 + 8) * SSTR + ks + 2 * t];
                afl[am][2] = *(const u32*)&sAl[(r0    ) * SSTR + ks + 2 * t + 8];
                afl[am][3] = *(const u32*)&sAl[(r0 + 8) * SSTR + ks + 2 * t + 8];
            }
            u32 bfh[8][2], bfl[8][2];
#pragma unroll
            for (int an = 0; an < 8; an++) {
                const int n = wn + an * 8 + g;
                bfh[an][0] = *(const u32*)&sBh[n * SSTR + ks + 2 * t];
                bfh[an][1] = *(const u32*)&sBh[n * SSTR + ks + 2 * t + 8];
                bfl[an][0] = *(const u32*)&sBl[n * SSTR + ks + 2 * t];
                bfl[an][1] = *(const u32*)&sBl[n * SSTR + ks + 2 * t + 8];
            }
#pragma unroll
            for (int am = 0; am < 2; am++)
#pragma unroll
                for (int an = 0; an < 8; an++) {
                    MMA_BF16(acc[am][an], afh[am], bfh[an]);
                    MMA_BF16(acc[am][an], afh[am], bfl[an]);
                    MMA_BF16(acc[am][an], afl[am], bfh[an]);
                }
        }
    }
}

// QKV: grid (M/128, NHEADS, 3), block 256. Writes split q/k/v in [b,h,s,d].
__global__ void __launch_bounds__(256) qkv_mma_kernel(
    const float* __restrict__ bQ, const float* __restrict__ bK, const float* __restrict__ bV)
{
    extern __shared__ __nv_bfloat16 smem[];
    const int mBase = blockIdx.x * 128;
    const int h     = blockIdx.y;
    const int which = blockIdx.z;
    const float* bias = ((which == 0) ? bQ : (which == 1) ? bK : bV) + h * DHEAD;
    __nv_bfloat16* dhi = (which == 0) ? gq_hi : (which == 1) ? gk_hi : gv_hi;
    __nv_bfloat16* dlo = (which == 0) ? gq_lo : (which == 1) ? gk_lo : gv_lo;
    const __nv_bfloat16* Bh = gw_hi + (size_t)(which * NHEADS + h) * DHEAD * DMODEL;
    const __nv_bfloat16* Bl = gw_lo + (size_t)(which * NHEADS + h) * DHEAD * DMODEL;

    float acc[2][8][4];
    gemm_split_core(gx_hi, gx_lo, Bh, Bl, mBase, acc, smem);

    const int tid = threadIdx.x, wid = tid >> 5, lane = tid & 31;
    const int wm = (wid & 3) * 32, wn = (wid >> 2) * 64;
    const int g = lane >> 2, t = lane & 3;

#pragma unroll
    for (int am = 0; am < 2; am++)
#pragma unroll
        for (int an = 0; an < 8; an++) {
            const int col = wn + an * 8 + 2 * t;
            const float b0 = bias[col], b1 = bias[col + 1];
#pragma unroll
            for (int half = 0; half < 2; half++) {
                const int m = mBase + wm + am * 16 + g + 8 * half;
                const int bb = m >> 11;
                const int s  = m & (SEQLEN - 1);
                const size_t dst = (((size_t)(bb * NHEADS + h) * SEQLEN + s) * DHEAD + col);
                float v0 = acc[am][an][2 * half + 0] + b0;
                float v1 = acc[am][an][2 * half + 1] + b1;
                __nv_bfloat16 h0, l0, h1, l1;
                split1(v0, h0, l0); split1(v1, h1, l1);
                __nv_bfloat162 hp; hp.x = h0; hp.y = h1;
                __nv_bfloat162 lp; lp.x = l0; lp.y = l1;
                *(__nv_bfloat162*)&dhi[dst] = hp;
                *(__nv_bfloat162*)&dlo[dst] = lp;
            }
        }
}

// out proj: grid (M/128, DMODEL/128), block 256
__global__ void __launch_bounds__(256) out_mma_kernel(
    const float* __restrict__ bO, float* __restrict__ out)
{
    extern __shared__ __nv_bfloat16 smem[];
    const int mBase = blockIdx.x * 128;
    const int nBase = blockIdx.y * 128;
    float acc[2][8][4];
    gemm_split_core(gz_hi, gz_lo,
                    gwo_hi + (size_t)nBase * DMODEL, gwo_lo + (size_t)nBase * DMODEL,
                    mBase, acc, smem);

    const int tid = threadIdx.x, wid = tid >> 5, lane = tid & 31;
    const int wm = (wid & 3) * 32, wn = (wid >> 2) * 64;
    const int g = lane >> 2, t = lane & 3;
    float* outBase = out + (size_t)mBase * DMODEL + nBase;
#pragma unroll
    for (int am = 0; am < 2; am++)
#pragma unroll
        for (int an = 0; an < 8; an++) {
            const int col = wn + an * 8 + 2 * t;
            const int r0 = wm + am * 16 + g;
            float b0 = bO[nBase + col], b1 = bO[nBase + col + 1];
            outBase[(size_t)r0 * DMODEL + col]           = acc[am][an][0] + b0;
            outBase[(size_t)r0 * DMODEL + col + 1]       = acc[am][an][1] + b1;
            outBase[(size_t)(r0 + 8) * DMODEL + col]     = acc[am][an][2] + b0;
            outBase[(size_t)(r0 + 8) * DMODEL + col + 1] = acc[am][an][3] + b1;
        }
}

// ---------------------------------------------------------------------------
// Tensor-core flash attention, cp.async 2-stage K/V pipeline.
// grid = (SEQLEN/128, NHEADS, BATCH), block = 256 (8 warps).
// ---------------------------------------------------------------------------
#define ASTR 136
#define AARR (64 * ASTR)            // elems per K/V array per stage
#define ASTAGE (4 * AARR)           // elems per KV stage
#define AQ (128 * ASTR)             // elems per Q array
#define ATTN_SMEM ((2 * AQ + 2 * ASTAGE) * 2)   // bytes

__global__ void __launch_bounds__(256, 1) attn_mma_kernel()
{
    const int qt = gridDim.x - 1 - blockIdx.x;   // heavy tiles first
    const int h  = blockIdx.y;
    const int b  = blockIdx.z;
    const int qBase = qt * 128;

    extern __shared__ __nv_bfloat16 smem[];
    __nv_bfloat16* sQh = smem;                 // [128][ASTR]
    __nv_bfloat16* sQl = sQh + AQ;
    __nv_bfloat16* kvs = sQl + AQ;             // 2 stages of [4][64][ASTR]

    const int tid = threadIdx.x;
    const int wid = tid >> 5;
    const int lane = tid & 31;
    const int g = lane >> 2;
    const int t = lane & 3;
    const int wrow = wid * 16;

    const size_t bh = (size_t)(b * NHEADS + h) * SEQLEN * DHEAD;
    const __nv_bfloat16* qh = gq_hi + bh;
    const __nv_bfloat16* ql = gq_lo + bh;
    const __nv_bfloat16* kh = gk_hi + bh;
    const __nv_bfloat16* kl = gk_lo + bh;
    const __nv_bfloat16* vh = gv_hi + bh;
    const __nv_bfloat16* vl = gv_lo + bh;

    const u32 kvbase = (u32)__cvta_generic_to_shared(kvs);

    // issue one K/V tile: 4 arrays x 64 rows x 16 chunks(16B)
    auto issue_kv = [&](int kBase, int st) {
        const u32 b0 = kvbase + (u32)st * (ASTAGE * 2);
#pragma unroll
        for (int it = 0; it < 4; it++) {
            const int idx = tid + it * 256;      // 0..1023
            const int r = idx >> 4;
            const int c = idx & 15;
            const u32 doff = (u32)(r * ASTR + c * 8) * 2;
            const size_t goff = (size_t)(kBase + r) * DHEAD + c * 8;
            cpa16(b0 + doff,                kh + goff);
            cpa16(b0 + AARR * 2 + doff,     kl + goff);
            cpa16(b0 + 2 * AARR * 2 + doff, vh + goff);
            cpa16(b0 + 3 * AARR * 2 + doff, vl + goff);
        }
        CP_COMMIT();
    };

    const int nkt = 2 * qt + 2;
    issue_kv(0, 0);

    // load Q tile (plain loads; overlaps with in-flight cp.async)
    for (int idx = tid; idx < 128 * 16; idx += 256) {
        const int r = idx >> 4, c8 = (idx & 15) * 8;
        *(uint4*)&sQh[r * ASTR + c8] = *(const uint4*)&qh[(size_t)(qBase + r) * DHEAD + c8];
        *(uint4*)&sQl[r * ASTR + c8] = *(const uint4*)&ql[(size_t)(qBase + r) * DHEAD + c8];
    }

    float o[16][4];
#pragma unroll
    for (int j = 0; j < 16; j++)
#pragma unroll
        for (int c = 0; c < 4; c++) o[j][c] = 0.f;
    float m0 = -1e30f, m1 = -1e30f, l0 = 0.f, l1 = 0.f;

    const float sl2e = 0.08838834764831845f * 1.4426950408889634f;

    for (int kt = 0; kt < nkt; kt++) {
        const int kBase = kt * 64;
        const int cur = kt & 1;
        __syncthreads();   // compute(kt-1) done -> safe to overwrite buf(1-cur)
        if (kt + 1 < nkt) {
            issue_kv((kt + 1) * 64, 1 - cur);
            CP_WAIT1();
        } else {
            CP_WAIT0();
        }
        __syncthreads();

        if (kBase > qBase + wrow + 15) continue;   // compute-only skip (syncs already done)

        const __nv_bfloat16* sKh = kvs + cur * ASTAGE;
        const __nv_bfloat16* sKl = sKh + AARR;
        const __nv_bfloat16* sVh = sKl + AARR;
        const __nv_bfloat16* sVl = sVh + AARR;

        // ---- S = Q K^T
        float sacc[8][4];
#pragma unroll
        for (int an = 0; an < 8; an++)
#pragma unroll
            for (int c = 0; c < 4; c++) sacc[an][c] = 0.f;

#pragma unroll
        for (int ks = 0; ks < DHEAD; ks += 16) {
            u32 ah[4], al[4];
            const int r0 = wrow + g;
            ah[0] = *(const u32*)&sQh[(r0    ) * ASTR + ks + 2 * t];
            ah[1] = *(const u32*)&sQh[(r0 + 8) * ASTR + ks + 2 * t];
            ah[2] = *(const u32*)&sQh[(r0    ) * ASTR + ks + 2 * t + 8];
            ah[3] = *(const u32*)&sQh[(r0 + 8) * ASTR + ks + 2 * t + 8];
            al[0] = *(const u32*)&sQl[(r0    ) * ASTR + ks + 2 * t];
            al[1] = *(const u32*)&sQl[(r0 + 8) * ASTR + ks + 2 * t];
            al[2] = *(const u32*)&sQl[(r0    ) * ASTR + ks + 2 * t + 8];
            al[3] = *(const u32*)&sQl[(r0 + 8) * ASTR + ks + 2 * t + 8];
#pragma unroll
            for (int an = 0; an < 8; an++) {
                const int n = an * 8 + g;
                u32 bh2[2], bl2[2];
                bh2[0] = *(const u32*)&sKh[n * ASTR + ks + 2 * t];
                bh2[1] = *(const u32*)&sKh[n * ASTR + ks + 2 * t + 8];
                bl2[0] = *(const u32*)&sKl[n * ASTR + ks + 2 * t];
                bl2[1] = *(const u32*)&sKl[n * ASTR + ks + 2 * t + 8];
                MMA_BF16(sacc[an], ah, bh2);
                MMA_BF16(sacc[an], ah, bl2);
                MMA_BF16(sacc[an], al, bh2);
            }
        }

        // ---- scale + causal mask (log2 domain)
        const int qr0 = qBase + wrow + g;
        const int qr1 = qr0 + 8;
#pragma unroll
        for (int an = 0; an < 8; an++) {
            const int c0 = kBase + an * 8 + 2 * t;
            sacc[an][0] = (c0     <= qr0) ? sacc[an][0] * sl2e : -1e30f;
            sacc[an][1] = (c0 + 1 <= qr0) ? sacc[an][1] * sl2e : -1e30f;
            sacc[an][2] = (c0     <= qr1) ? sacc[an][2] * sl2e : -1e30f;
            sacc[an][3] = (c0 + 1 <= qr1) ? sacc[an][3] * sl2e : -1e30f;
        }

        // ---- row max
        float mx0 = -1e30f, mx1 = -1e30f;
#pragma unroll
        for (int an = 0; an < 8; an++) {
            mx0 = fmaxf(mx0, fmaxf(sacc[an][0], sacc[an][1]));
            mx1 = fmaxf(mx1, fmaxf(sacc[an][2], sacc[an][3]));
        }
        mx0 = fmaxf(mx0, __shfl_xor_sync(0xffffffffu, mx0, 1));
        mx0 = fmaxf(mx0, __shfl_xor_sync(0xffffffffu, mx0, 2));
        mx1 = fmaxf(mx1, __shfl_xor_sync(0xffffffffu, mx1, 1));
        mx1 = fmaxf(mx1, __shfl_xor_sync(0xffffffffu, mx1, 2));

        const float mn0 = fmaxf(m0, mx0), mn1 = fmaxf(m1, mx1);
        const float al0 = ex2f(m0 - mn0), al1 = ex2f(m1 - mn1);
        m0 = mn0; m1 = mn1;

        // ---- p = 2^(s - m), row sums
        float s0 = 0.f, s1 = 0.f;
#pragma unroll
        for (int an = 0; an < 8; an++) {
            sacc[an][0] = ex2f(sacc[an][0] - mn0);
            sacc[an][1] = ex2f(sacc[an][1] - mn0);
            sacc[an][2] = ex2f(sacc[an][2] - mn1);
            sacc[an][3] = ex2f(sacc[an][3] - mn1);
            s0 += sacc[an][0] + sacc[an][1];
            s1 += sacc[an][2] + sacc[an][3];
        }
        s0 += __shfl_xor_sync(0xffffffffu, s0, 1);
        s0 += __shfl_xor_sync(0xffffffffu, s0, 2);
        s1 += __shfl_xor_sync(0xffffffffu, s1, 1);
        s1 += __shfl_xor_sync(0xffffffffu, s1, 2);
        l0 = l0 * al0 + s0;
        l1 = l1 * al1 + s1;

#pragma unroll
        for (int j = 0; j < 16; j++) {
            o[j][0] *= al0; o[j][1] *= al0;
            o[j][2] *= al1; o[j][3] *= al1;
        }

        // ---- O += P V
        const u16* sVh16 = (const u16*)sVh;
        const u16* sVl16 = (const u16*)sVl;
#pragma unroll
        for (int jp = 0; jp < 4; jp++) {
            u32 aph[4], apl[4];
            {
                float p00 = sacc[2 * jp][0],     p01 = sacc[2 * jp][1];
                float p02 = sacc[2 * jp][2],     p03 = sacc[2 * jp][3];
                float p10 = sacc[2 * jp + 1][0], p11 = sacc[2 * jp + 1][1];
                float p12 = sacc[2 * jp + 1][2], p13 = sacc[2 * jp + 1][3];
                __nv_bfloat16 hh, ll;
                float h00, h01, h02, h03, h10, h11, h12, h13;
                split1(p00, hh, ll); h00 = __bfloat162float(hh);
                split1(p01, hh, ll); h01 = __bfloat162float(hh);
                split1(p02, hh, ll); h02 = __bfloat162float(hh);
                split1(p03, hh, ll); h03 = __bfloat162float(hh);
                split1(p10, hh, ll); h10 = __bfloat162float(hh);
                split1(p11, hh, ll); h11 = __bfloat162float(hh);
                split1(p12, hh, ll); h12 = __bfloat162float(hh);
                split1(p13, hh, ll); h13 = __bfloat162float(hh);
                aph[0] = pack2bf(h00, h01);
                aph[1] = pack2bf(h02, h03);
                aph[2] = pack2bf(h10, h11);
                aph[3] = pack2bf(h12, h13);
                apl[0] = pack2bf(p00 - h00, p01 - h01);
                apl[1] = pack2bf(p02 - h02, p03 - h03);
                apl[2] = pack2bf(p10 - h10, p11 - h11);
                apl[3] = pack2bf(p12 - h12, p13 - h13);
            }
            const int ks = 16 * jp;
#pragma unroll
            for (int an = 0; an < 16; an++) {
                const int n = an * 8 + g;
                u32 bh2[2], bl2[2];
                {
                    u32 v0 = sVh16[(ks + 2 * t)     * ASTR + n];
                    u32 v1 = sVh16[(ks + 2 * t + 1) * ASTR + n];
                    u32 v8 = sVh16[(ks + 2 * t + 8) * ASTR + n];
                    u32 v9 = sVh16[(ks + 2 * t + 9) * ASTR + n];
                    bh2[0] = v0 | (v1 << 16);
                    bh2[1] = v8 | (v9 << 16);
                    v0 = sVl16[(ks + 2 * t)     * ASTR + n];
                    v1 = sVl16[(ks + 2 * t + 1) * ASTR + n];
                    v8 = sVl16[(ks + 2 * t + 8) * ASTR + n];
                    v9 = sVl16[(ks + 2 * t + 9) * ASTR + n];
                    bl2[0] = v0 | (v1 << 16);
                    bl2[1] = v8 | (v9 << 16);
                }
                MMA_BF16(o[an], aph, bh2);
                MMA_BF16(o[an], aph, bl2);
                MMA_BF16(o[an], apl, bh2);
            }
        }
    }

    // ---- epilogue
    const float inv0 = 1.f / l0;
    const float inv1 = 1.f / l1;
    const int r0 = qBase + wrow + g;
#pragma unroll
    for (int an = 0; an < 16; an++) {
        const int col = an * 8 + 2 * t;
#pragma unroll
        for (int half = 0; half < 2; half++) {
            const int row = r0 + 8 * half;
            const float inv = half ? inv1 : inv0;
            float z0 = o[an][2 * half + 0] * inv;
            float z1 = o[an][2 * half + 1] * inv;
            __nv_bfloat16 h0, lo0, h1, lo1;
            split1(z0, h0, lo0); split1(z1, h1, lo1);
            __nv_bfloat162 hp; hp.x = h0; hp.y = h1;
            __nv_bfloat162 lp; lp.x = lo0; lp.y = lo1;
            const size_t dst = ((size_t)(b * SEQLEN + row) * DMODEL + h * DHEAD + col);
            *(__nv_bfloat162*)&gz_hi[dst] = hp;
            *(__nv_bfloat162*)&gz_lo[dst] = lp;
        }
    }
}

// ---------------------------------------------------------------------------
// Launch
// ---------------------------------------------------------------------------
extern "C" void kernel_launch(void* const* d_in, const int* in_sizes, int n_in,
                              void* d_out, int out_size)
{
    const float* x  = (const float*)d_in[0];
    const float* Wq = (const float*)d_in[1];
    const float* Wk = (const float*)d_in[2];
    const float* Wv = (const float*)d_in[3];
    const float* Wo = (const float*)d_in[4];
    const float* bQ = (const float*)d_in[5];
    const float* bK = (const float*)d_in[6];
    const float* bV = (const float*)d_in[7];
    const float* bO = (const float*)d_in[8];
    float* out = (float*)d_out;

    static bool attr_set = false;
    if (!attr_set) {
        cudaFuncSetAttribute(qkv_mma_kernel, cudaFuncAttributeMaxDynamicSharedMemorySize, GEMM_SMEM);
        cudaFuncSetAttribute(out_mma_kernel, cudaFuncAttributeMaxDynamicSharedMemorySize, GEMM_SMEM);
        cudaFuncSetAttribute(attn_mma_kernel, cudaFuncAttributeMaxDynamicSharedMemorySize, ATTN_SMEM);
        attr_set = true;
    }

    // 0) split/transposes
    split_x_kernel<<<(MTOT * DMODEL / 2) / 256, 256>>>(x);
    split_w_kernel<<<dim3(DMODEL / 32, DHEAD / 32, 3 * NHEADS), dim3(32, 8)>>>(Wq, Wk, Wv);
    split_wo_kernel<<<dim3(DMODEL / 32, DMODEL / 32), dim3(32, 8)>>>(Wo);

    // 1) QKV projections (tensor cores, pipelined)
    qkv_mma_kernel<<<dim3(MTOT / 128, NHEADS, 3), 256, GEMM_SMEM>>>(bQ, bK, bV);

    // 2) tensor-core flash attention (pipelined K/V)
    attn_mma_kernel<<<dim3(SEQLEN / 128, NHEADS, BATCH), 256, ATTN_SMEM>>>();

    // 3) output projection (tensor cores, pipelined)
    out_mma_kernel<<<dim3(MTOT / 128, DMODEL / 128), 256, GEMM_SMEM>>>(bO, out);

    (void)in_sizes; (void)n_in; (void)out_size;
}